// round 7
// baseline (speedup 1.0000x reference)
#include <cuda_runtime.h>
#include <math.h>

#define Bn 512
#define Hn 1024
#define Sn 1024
#define Dn 128
#define Kn 32

// Output layout: [read (B*D)] [new_memory (B*S*D)] [weights (B*S)]
#define READ_OFF 0
#define MEM_OFF  (Bn*Dn)
#define W_OFF    (Bn*Dn + (size_t)Bn*Sn*Dn)

#define NTILE 16384      // 16KB tiles of new_memory (1024 float4 each)
#define NBLK  592        // 148 SMs x 4 resident CTAs (one wave)
#define NCMP  256        // compute-role blocks
#define NSPARE (NBLK - NCMP)     // 336 prefix-copy blocks
#define QPRE  8                  // prefix tiles per spare block
#define PRE   (NSPARE * QPRE)    // 2688 tiles = batches [0, 84)
#define PREB  84                 // prefix batches

// Scratch + sync state (no allocation allowed -> device globals)
__device__ float4 g_query[Bn * (Dn/4)];
__device__ float4 g_value[Bn * (Dn/4)];
__device__ float  g_logits[Bn * Sn];
__device__ float  g_gate[Bn];
__device__ int    g_barA, g_barB, g_barC;

#define DYN_SMEM 33792   // max(qv 32768, logits 33792, batch 4096)

__global__ void init_kernel() { g_barA = 0; g_barB = 0; g_barC = 0; }

// Block-consistent wait on a monotone counter.
#define WAIT_GE(ctr, tgt)                                       \
    for (;;) {                                                  \
        if (threadIdx.x == 0) s_flag = (atomicAdd(&(ctr), 0) >= (tgt)); \
        __syncthreads();                                        \
        int f_ = s_flag;                                        \
        __syncthreads();                                        \
        if (f_) break;                                          \
        __nanosleep(200);                                       \
    }

#define ARRIVE(ctr)                                             \
    do { __threadfence(); __syncthreads();                      \
         if (threadIdx.x == 0) atomicAdd(&(ctr), 1); } while (0)

__global__ __launch_bounds__(256, 4)
void fused_kernel(const float* __restrict__ latent,
                  const float* __restrict__ memory,
                  const float* __restrict__ key,
                  const float* __restrict__ Wq, const float* __restrict__ bq,
                  const float* __restrict__ Wv, const float* __restrict__ bv,
                  const float* __restrict__ wg, const float* __restrict__ bg,
                  const float* __restrict__ wd, const float* __restrict__ bd,
                  const float* __restrict__ wp, const float* __restrict__ bp,
                  float* __restrict__ out)
{
    extern __shared__ char dynbuf[];
    __shared__ int   s_flag;
    __shared__ int   sti[2][Kn];
    __shared__ float stw[2][Kn];
    __shared__ float sgate[2];
    __shared__ float rd[Dn];
    __shared__ float r3[24];

    const int bid = blockIdx.x;
    const int tid = threadIdx.x;
    const float4* mem4 = (const float4*)memory;
    float4* dstm = (float4*)(out + MEM_OFF);
    const float*  wts = out + W_OFF;

    if (bid >= NCMP) {
        // =========== spare blocks: prefix pure-copy, then barC ===========
        const int c0 = bid - NCMP;
        #pragma unroll 1
        for (int k = 0; k < QPRE; k++) {
            size_t t = (size_t)(c0 * QPRE + k);
            const float4* s = mem4 + t * 1024;
            float4*       d = dstm + t * 1024;
            #pragma unroll
            for (int j = 0; j < 4; j++) {
                int i = tid + j * 256;
                __stcs(&d[i], __ldcs(&s[i]));
            }
        }
        ARRIVE(g_barC);
        WAIT_GE(g_barC, NBLK);
        __threadfence();
    } else {
        // ================= compute blocks (0..255) ========================

        // ---- Phase A: qv, 128 tasks (mat, 8 batches); blocks 0..127 ----
        if (bid < 128) {
            float4* sm = (float4*)dynbuf;               // 2048 f4 = 32KB
            const int mat = bid >> 6;
            const int b0  = (bid & 63) * 8;
            const float4* W4    = (const float4*)(mat ? Wv : Wq);
            const float4* bias4 = (const float4*)(mat ? bv : bq);
            float4*       out4  = mat ? g_value : g_query;

            const int dq = tid & 31;
            const int hs = tid >> 5;

            {
                const float4* src = (const float4*)(latent + (size_t)b0 * Hn);
                #pragma unroll
                for (int i = 0; i < 8; i++) sm[tid + i * 256] = src[tid + i * 256];
            }
            __syncthreads();

            float4 acc[8];
            #pragma unroll
            for (int j = 0; j < 8; j++) acc[j] = make_float4(0.f, 0.f, 0.f, 0.f);

            const int hbase = hs * 128;
            #pragma unroll 2
            for (int c = 0; c < 32; c++) {
                const int h0 = hbase + c * 4;
                float4 w0 = W4[(size_t)(h0 + 0) * 32 + dq];
                float4 w1 = W4[(size_t)(h0 + 1) * 32 + dq];
                float4 w2 = W4[(size_t)(h0 + 2) * 32 + dq];
                float4 w3 = W4[(size_t)(h0 + 3) * 32 + dq];
                #pragma unroll
                for (int j = 0; j < 8; j++) {
                    float4 lf = sm[j * 256 + hs * 32 + c];
                    acc[j].x += lf.x * w0.x + lf.y * w1.x + lf.z * w2.x + lf.w * w3.x;
                    acc[j].y += lf.x * w0.y + lf.y * w1.y + lf.z * w2.y + lf.w * w3.y;
                    acc[j].z += lf.x * w0.z + lf.y * w1.z + lf.z * w2.z + lf.w * w3.z;
                    acc[j].w += lf.x * w0.w + lf.y * w1.w + lf.z * w2.w + lf.w * w3.w;
                }
            }
            __syncthreads();

            #pragma unroll
            for (int j = 0; j < 8; j++) sm[hs * 256 + j * 32 + dq] = acc[j];
            __syncthreads();

            {
                const int j2  = tid >> 5;
                const int dq2 = tid & 31;
                float4 s = make_float4(0.f, 0.f, 0.f, 0.f);
                #pragma unroll
                for (int h = 0; h < 8; h++) {
                    float4 v = sm[h * 256 + j2 * 32 + dq2];
                    s.x += v.x; s.y += v.y; s.z += v.z; s.w += v.w;
                }
                float4 bb = bias4[dq2];
                s.x += bb.x; s.y += bb.y; s.z += bb.z; s.w += bb.w;
                out4[(size_t)(b0 + j2) * 32 + dq2] = s;
            }
            ARRIVE(g_barA);
        }
        WAIT_GE(g_barA, 128);
        __threadfence();

        // ---- Phase B: logits, 512 tiles over 256 blocks (2 each) ----
        {
            float4* qs = (float4*)dynbuf;       // [32][33]
            float4* ks = qs + 32 * 33;          // [32][33]
            const float4* k4 = (const float4*)key;
            const int rb = tid >> 5;            // warp-uniform -> broadcast LDS
            const int c  = tid & 31;

            for (int j = 0; j < 2; j++) {
                const int t  = bid + NCMP * j;
                const int b0 = (t >> 5) * 32;
                const int s0 = (t & 31) * 32;
                __syncthreads();
                for (int i = tid; i < 1024; i += 256) {
                    int r = i >> 5, cc = i & 31;
                    qs[r * 33 + cc] = g_query[(size_t)(b0 + r) * 32 + cc];
                    ks[r * 33 + cc] = k4[(size_t)(s0 + r) * 32 + cc];
                }
                __syncthreads();

                float a0 = 0.f, a1 = 0.f, a2 = 0.f, a3 = 0.f;
                #pragma unroll 8
                for (int c4 = 0; c4 < 32; c4++) {
                    float4 kv = ks[c * 33 + c4];
                    float4 q0 = qs[(rb     ) * 33 + c4];
                    float4 q1 = qs[(rb +  8) * 33 + c4];
                    float4 q2 = qs[(rb + 16) * 33 + c4];
                    float4 q3 = qs[(rb + 24) * 33 + c4];
                    a0 += q0.x*kv.x + q0.y*kv.y + q0.z*kv.z + q0.w*kv.w;
                    a1 += q1.x*kv.x + q1.y*kv.y + q1.z*kv.z + q1.w*kv.w;
                    a2 += q2.x*kv.x + q2.y*kv.y + q2.z*kv.z + q2.w*kv.w;
                    a3 += q3.x*kv.x + q3.y*kv.y + q3.z*kv.z + q3.w*kv.w;
                }
                g_logits[(size_t)(b0 + rb     ) * Sn + s0 + c] = a0;
                g_logits[(size_t)(b0 + rb +  8) * Sn + s0 + c] = a1;
                g_logits[(size_t)(b0 + rb + 16) * Sn + s0 + c] = a2;
                g_logits[(size_t)(b0 + rb + 24) * Sn + s0 + c] = a3;
            }
        }
        ARRIVE(g_barB);
        WAIT_GE(g_barB, NCMP);
        __threadfence();

        // ---- Phase C: batch (2 batches per block) ----
        {
            float* sl = (float*)dynbuf;
            for (int j = 0; j < 2; j++) {
                const int b = bid * 2 + j;
                __syncthreads();
                for (int i = tid; i < Sn; i += 256) sl[i] = g_logits[(size_t)b * Sn + i];
                __syncthreads();

                if (tid < 32) {
                    const int lane = tid;
                    for (int it = 0; it < Kn; it++) {
                        float bv2 = -1e30f; int bi = 0;
                        #pragma unroll
                        for (int k = 0; k < 32; k++) {
                            float v = sl[lane + 32 * k];
                            if (v > bv2) { bv2 = v; bi = lane + 32 * k; }
                        }
                        #pragma unroll
                        for (int o = 16; o; o >>= 1) {
                            float ov = __shfl_xor_sync(0xffffffffu, bv2, o);
                            int   oi = __shfl_xor_sync(0xffffffffu, bi, o);
                            if (ov > bv2 || (ov == bv2 && oi < bi)) { bv2 = ov; bi = oi; }
                        }
                        if ((bi & 31) == lane) sl[bi] = -1e30f;
                        if (lane == 0) { sti[j][it] = bi; stw[j][it] = bv2; }
                        __syncwarp();
                    }
                    float m = stw[j][0];
                    float e = __expf(stw[j][lane] - m);
                    float s = e;
                    #pragma unroll
                    for (int o = 16; o; o >>= 1) s += __shfl_xor_sync(0xffffffffu, s, o);
                    stw[j][lane] = e / s;
                    __syncwarp();
                }
                __syncthreads();

                // weights row: zero + scatter
                float* wout = out + W_OFF + (size_t)b * Sn;
                for (int i = tid; i < Sn; i += 256) wout[i] = 0.f;
                __syncthreads();
                if (tid < Kn) wout[sti[j][tid]] = stw[j][tid];

                if (tid < Dn) {
                    float acc = 0.f;
                    #pragma unroll 8
                    for (int k = 0; k < Kn; k++)
                        acc += stw[j][k] * memory[((size_t)b * Sn + sti[j][k]) * Dn + tid];
                    out[READ_OFF + (size_t)b * Dn + tid] = acc;
                    rd[tid] = acc;
                }
                __syncthreads();

                float pg = 0.f, pd = 0.f, pp = 0.f;
                const float* latb = latent + (size_t)b * Hn;
                for (int i = tid; i < Hn; i += 256) {
                    float x = latb[i];
                    pg += x * wg[i];
                    pd += x * wd[i];
                    pp += x * wp[i];
                }
                if (tid < Dn) {
                    float x = rd[tid];
                    pg += x * wg[Hn + tid];
                    pd += x * wd[Hn + tid];
                }
                #pragma unroll
                for (int o = 16; o; o >>= 1) {
                    pg += __shfl_xor_sync(0xffffffffu, pg, o);
                    pd += __shfl_xor_sync(0xffffffffu, pd, o);
                    pp += __shfl_xor_sync(0xffffffffu, pp, o);
                }
                const int wpid = tid >> 5, lane = tid & 31;
                if (lane == 0) { r3[wpid] = pg; r3[8 + wpid] = pd; r3[16 + wpid] = pp; }
                __syncthreads();
                if (tid == 0) {
                    float G = 0.f, Dv = 0.f, P = 0.f;
                    #pragma unroll
                    for (int i = 0; i < 8; i++) { G += r3[i]; Dv += r3[8 + i]; P += r3[16 + i]; }
                    float gate = 1.f / (1.f + __expf(-(G + bg[0])));
                    float dmd  = tanhf(Dv + bd[0]);
                    gate = gate * (0.75f + 0.5f * (dmd + 1.0f) * 0.5f);
                    gate = fminf(fmaxf(gate, 0.f), 1.f);
                    float ph = P + bp[0];
                    gate *= 0.5f * (1.f + cosf(ph));
                    g_gate[b] = gate;
                    sgate[j] = gate;
                }
                __syncthreads();
            }
        }
        ARRIVE(g_barC);
        WAIT_GE(g_barC, NBLK);
        __threadfence();

        // ---- fixup of prefix batches (<PREB) by their phase-C owners ----
        for (int j = 0; j < 2; j++) {
            const int b = bid * 2 + j;
            if (b >= PREB) break;
            #pragma unroll
            for (int i = 0; i < 4; i++) {
                int idx = tid + i * 256;
                int r   = idx >> 5;
                int q   = idx & 31;
                int s   = sti[j][r];
                float w = sgate[j] * stw[j][r];
                size_t g = ((size_t)b * Sn + s) * 32 + q;
                float4 m = mem4[g];
                float4 v = g_value[b * 32 + q];
                m.x += w * (v.x - m.x);
                m.y += w * (v.y - m.y);
                m.z += w * (v.z - m.z);
                m.w += w * (v.w - m.w);
                dstm[g] = m;
            }
        }
    }

    // ======== Phase D (all blocks): fused copy_update on tiles [PRE,NTILE) ==
    for (int t = PRE + bid; t < NTILE; t += NBLK) {
        size_t base = (size_t)t * 1024 + tid;
        #pragma unroll
        for (int j = 0; j < 4; j++) {
            size_t g = base + (size_t)j * 256;
            int row = (int)(g >> 5);          // b*S + s
            int bb  = row >> 10;
            float w = __ldg(&wts[row]);       // warp-uniform broadcast
            float4 m = __ldcs(&mem4[g]);
            if (w != 0.f) {
                float gw = g_gate[bb] * w;
                float4 v = g_value[(size_t)bb * 32 + (g & 31)];
                m.x = (1.f - gw) * m.x + gw * v.x;
                m.y = (1.f - gw) * m.y + gw * v.y;
                m.z = (1.f - gw) * m.z + gw * v.z;
                m.w = (1.f - gw) * m.w + gw * v.w;
            }
            __stcs(&dstm[g], m);
        }
    }
}

// ---------------------------------------------------------------------------
extern "C" void kernel_launch(void* const* d_in, const int* in_sizes, int n_in,
                              void* d_out, int out_size)
{
    const float* latent    = (const float*)d_in[0];
    const float* memory    = (const float*)d_in[1];
    const float* rq_w      = (const float*)d_in[2];
    const float* rq_b      = (const float*)d_in[3];
    const float* mem_key   = (const float*)d_in[4];
    const float* wg_w      = (const float*)d_in[5];
    const float* wg_b      = (const float*)d_in[6];
    const float* wd_w      = (const float*)d_in[7];
    const float* wd_b      = (const float*)d_in[8];
    const float* wp_w      = (const float*)d_in[9];
    const float* wp_b      = (const float*)d_in[10];
    const float* wv_w      = (const float*)d_in[11];
    const float* wv_b      = (const float*)d_in[12];
    float* out = (float*)d_out;

    init_kernel<<<1, 1>>>();
    fused_kernel<<<NBLK, 256, DYN_SMEM>>>(latent, memory, mem_key,
                                          rq_w, rq_b, wv_w, wv_b,
                                          wg_w, wg_b, wd_w, wd_b, wp_w, wp_b,
                                          out);
}